// round 1
// baseline (speedup 1.0000x reference)
#include <cuda_runtime.h>
#include <stdint.h>

#define NEGF (-1e9f)

// ---------------- scratch (alloc-free: __device__ globals) ----------------
// S / P buffer: [16, 1024, 2048] fp32 = 134 MB
__device__ float g_S[16u * 1024u * 2048u];
// V'^T buffer:  [16, 256, 2048] fp32 = 33.5 MB   (V'^T[b][o][k] = sum_v W[o][v]*V[b][k][v])
__device__ float g_Vt[16u * 256u * 2048u];

// ---------------- TF32 helpers ----------------
__device__ __forceinline__ float tf32r(float x) {
    uint32_t u;
    asm("cvt.rna.tf32.f32 %0, %1;" : "=r"(u) : "f"(x));
    return __uint_as_float(u);
}

__device__ __forceinline__ void mma_tf32(float c[4], const uint32_t a[4], const uint32_t b[2]) {
    asm volatile(
        "mma.sync.aligned.m16n8k8.row.col.f32.tf32.tf32.f32 "
        "{%0,%1,%2,%3}, {%4,%5,%6,%7}, {%8,%9}, {%0,%1,%2,%3};"
        : "+f"(c[0]), "+f"(c[1]), "+f"(c[2]), "+f"(c[3])
        : "r"(a[0]), "r"(a[1]), "r"(a[2]), "r"(a[3]), "r"(b[0]), "r"(b[1]));
}

// ---------------- generic batched TF32 GEMM ----------------
// C[z][m][n] = sum_k A[z][m][k] * B[z][n][k]     (both operands K-major)
// EPI: 0 = plain, 1 = scale + mask(-1e9), 2 = +bias[n]
constexpr int BM = 128, BN = 128, BK = 32, BKP = 36;

template <int EPI>
__global__ __launch_bounds__(256)
void gemm_tf32(const float* __restrict__ Ag, const float* __restrict__ Bg,
               float* __restrict__ Cg,
               int M, int N, int K,
               long long sA, long long sB, long long sC,
               const int* __restrict__ maskg, long long sMask,
               const float* __restrict__ bias, float scale)
{
    __shared__ __align__(16) float As[BM * BKP];
    __shared__ __align__(16) float Bs[BN * BKP];

    const int tid  = threadIdx.x;
    const int lane = tid & 31;
    const int warp = tid >> 5;
    const int wm = (warp & 1) * 64;       // 2 warps along M
    const int wn = (warp >> 1) * 32;      // 4 warps along N
    const int z  = blockIdx.z;
    const int m0 = blockIdx.y * BM;
    const int n0 = blockIdx.x * BN;

    const float* A = Ag + (size_t)z * sA;
    const float* B = Bg + (size_t)z * sB;

    const int lr = tid >> 3;              // 0..31  (row within 32-row slab)
    const int lc = (tid & 7) * 4;         // 0..28  (float4 col within BK)

    float acc[4][4][4];
#pragma unroll
    for (int i = 0; i < 4; i++)
#pragma unroll
        for (int j = 0; j < 4; j++)
#pragma unroll
            for (int r = 0; r < 4; r++) acc[i][j][r] = 0.0f;

    float4 ra[4], rb[4];
#pragma unroll
    for (int i = 0; i < 4; i++) {
        ra[i] = *(const float4*)(A + (size_t)(m0 + lr + 32 * i) * K + lc);
        rb[i] = *(const float4*)(B + (size_t)(n0 + lr + 32 * i) * K + lc);
    }

    const int ktiles = K / BK;
    for (int kb = 0; kb < ktiles; ++kb) {
        __syncthreads();   // previous compute done before overwriting smem
#pragma unroll
        for (int i = 0; i < 4; i++) {
            float4 v = ra[i];
            v.x = tf32r(v.x); v.y = tf32r(v.y); v.z = tf32r(v.z); v.w = tf32r(v.w);
            *(float4*)&As[(lr + 32 * i) * BKP + lc] = v;
            float4 w = rb[i];
            w.x = tf32r(w.x); w.y = tf32r(w.y); w.z = tf32r(w.z); w.w = tf32r(w.w);
            *(float4*)&Bs[(lr + 32 * i) * BKP + lc] = w;
        }
        __syncthreads();

        if (kb + 1 < ktiles) {            // issue next-tile LDGs, overlap with MMAs
            const int koff = (kb + 1) * BK + lc;
#pragma unroll
            for (int i = 0; i < 4; i++) {
                ra[i] = *(const float4*)(A + (size_t)(m0 + lr + 32 * i) * K + koff);
                rb[i] = *(const float4*)(B + (size_t)(n0 + lr + 32 * i) * K + koff);
            }
        }

#pragma unroll
        for (int ks = 0; ks < 4; ++ks) {
            const int k0 = ks * 8;
            uint32_t af[4][2][2], bf[4][2];
#pragma unroll
            for (int mi = 0; mi < 4; mi++) {
                const int r = wm + mi * 16 + (lane >> 2);
                const int c = k0 + (lane & 3);
                af[mi][0][0] = __float_as_uint(As[r * BKP + c]);          // a0
                af[mi][0][1] = __float_as_uint(As[(r + 8) * BKP + c]);    // a1
                af[mi][1][0] = __float_as_uint(As[r * BKP + c + 4]);      // a2
                af[mi][1][1] = __float_as_uint(As[(r + 8) * BKP + c + 4]);// a3
            }
#pragma unroll
            for (int ni = 0; ni < 4; ni++) {
                const int r = wn + ni * 8 + (lane >> 2);
                const int c = k0 + (lane & 3);
                bf[ni][0] = __float_as_uint(Bs[r * BKP + c]);
                bf[ni][1] = __float_as_uint(Bs[r * BKP + c + 4]);
            }
#pragma unroll
            for (int mi = 0; mi < 4; mi++) {
                uint32_t a4[4] = {af[mi][0][0], af[mi][0][1], af[mi][1][0], af[mi][1][1]};
#pragma unroll
                for (int ni = 0; ni < 4; ni++)
                    mma_tf32(acc[mi][ni], a4, bf[ni]);
            }
        }
    }

    // ---------------- epilogue ----------------
    float* C = Cg + (size_t)z * sC;
    const int* Mk = (EPI == 1) ? (maskg + (size_t)z * sMask) : nullptr;

#pragma unroll
    for (int mi = 0; mi < 4; mi++) {
#pragma unroll
        for (int ni = 0; ni < 4; ni++) {
            const int row0 = m0 + wm + mi * 16 + (lane >> 2);
            const int col  = n0 + wn + ni * 8 + (lane & 3) * 2;
#pragma unroll
            for (int h = 0; h < 2; ++h) {
                const int row = row0 + h * 8;
                float v0 = acc[mi][ni][2 * h];
                float v1 = acc[mi][ni][2 * h + 1];
                if (EPI == 1) {
                    v0 *= scale; v1 *= scale;
                    int2 mk = *(const int2*)(Mk + (size_t)row * N + col);
                    if (mk.x == 0) v0 = NEGF;
                    if (mk.y == 0) v1 = NEGF;
                } else if (EPI == 2) {
                    v0 += bias[col];
                    v1 += bias[col + 1];
                }
                float2 o; o.x = v0; o.y = v1;
                *(float2*)(C + (size_t)row * N + col) = o;
            }
        }
    }
}

// ---------------- row softmax over NK=2048 ----------------
__global__ __launch_bounds__(256)
void softmax_rows(float* __restrict__ S)
{
    const int NKc = 2048;
    float* row = S + (size_t)blockIdx.x * NKc;
    const int tid = threadIdx.x;

    float4 a = reinterpret_cast<float4*>(row)[tid];
    float4 b = reinterpret_cast<float4*>(row)[tid + 256];

    float m = fmaxf(fmaxf(fmaxf(a.x, a.y), fmaxf(a.z, a.w)),
                    fmaxf(fmaxf(b.x, b.y), fmaxf(b.z, b.w)));
#pragma unroll
    for (int o = 16; o; o >>= 1) m = fmaxf(m, __shfl_xor_sync(0xffffffffu, m, o));

    __shared__ float red[8];
    if ((tid & 31) == 0) red[tid >> 5] = m;
    __syncthreads();
    m = red[0];
#pragma unroll
    for (int i = 1; i < 8; i++) m = fmaxf(m, red[i]);

    a.x = __expf(a.x - m); a.y = __expf(a.y - m); a.z = __expf(a.z - m); a.w = __expf(a.w - m);
    b.x = __expf(b.x - m); b.y = __expf(b.y - m); b.z = __expf(b.z - m); b.w = __expf(b.w - m);

    float s = (a.x + a.y) + (a.z + a.w) + (b.x + b.y) + (b.z + b.w);
#pragma unroll
    for (int o = 16; o; o >>= 1) s += __shfl_xor_sync(0xffffffffu, s, o);

    __syncthreads();   // everyone done reading red[] for max
    if ((tid & 31) == 0) red[tid >> 5] = s;
    __syncthreads();
    s = red[0];
#pragma unroll
    for (int i = 1; i < 8; i++) s += red[i];

    const float inv = 1.0f / s;
    a.x *= inv; a.y *= inv; a.z *= inv; a.w *= inv;
    b.x *= inv; b.y *= inv; b.z *= inv; b.w *= inv;

    reinterpret_cast<float4*>(row)[tid]       = a;
    reinterpret_cast<float4*>(row)[tid + 256] = b;
}

// ---------------- launch ----------------
extern "C" void kernel_launch(void* const* d_in, const int* in_sizes, int n_in,
                              void* d_out, int out_size)
{
    const float* keys    = (const float*)d_in[0];   // [16, 2048, 512]
    const float* queries = (const float*)d_in[1];   // [16, 1024, 512]
    const float* values  = (const float*)d_in[2];   // [16, 2048, 512]
    const int*   mask    = (const int*)  d_in[3];   // [16, 1024, 2048]
    const float* W       = (const float*)d_in[4];   // [256, 512]
    const float* bias    = (const float*)d_in[5];   // [256]
    float* out = (float*)d_out;                     // [16, 1024, 256]

    const int B = 16, NQ = 1024, NK = 2048, D = 512, V = 512, O = 256;
    const float scale = 1.0f / sqrtf(512.0f);       // KQ = 512

    float* S  = nullptr;
    float* Vt = nullptr;
    cudaGetSymbolAddress((void**)&S,  g_S);
    cudaGetSymbolAddress((void**)&Vt, g_Vt);

    dim3 blk(256);

    // K0: V'^T[b][o][k] = sum_v W[o][v] * values[b][k][v]    (A = W, no batch stride)
    gemm_tf32<0><<<dim3(NK / BN, O / BM, B), blk>>>(
        W, values, Vt, O, NK, V,
        0LL, (long long)NK * V, (long long)O * NK,
        nullptr, 0LL, nullptr, 0.0f);

    // K1: S[b][q][k] = scale * <Q[b][q], K[b][k]>, masked -> -1e9
    gemm_tf32<1><<<dim3(NK / BN, NQ / BM, B), blk>>>(
        queries, keys, S, NQ, NK, D,
        (long long)NQ * D, (long long)NK * D, (long long)NQ * NK,
        mask, (long long)NQ * NK, nullptr, scale);

    // K2: softmax over last dim
    softmax_rows<<<B * NQ, 256>>>(S);

    // K3: out[b][q][o] = sum_k P[b][q][k] * V'^T[b][o][k] + bias[o]
    gemm_tf32<2><<<dim3(O / BN, NQ / BM, B), blk>>>(
        S, Vt, out, NQ, O, NK,
        (long long)NQ * NK, (long long)O * NK, (long long)NQ * O,
        nullptr, 0LL, bias, 1.0f);
}

// round 3
// speedup vs baseline: 1.0500x; 1.0500x over previous
#include <cuda_runtime.h>
#include <stdint.h>

#define NEGF (-1e9f)

// ---------------- scratch (alloc-free: __device__ globals) ----------------
__device__ float g_S [16u * 1024u * 2048u];   // logits / probs  [B,NQ,NK]
__device__ float g_Vt[16u * 256u  * 2048u];   // V'^T = W @ V^T  [B,O,NK]

// ---------------- helpers ----------------
__device__ __forceinline__ uint32_t smem_u32(const void* p) {
    uint32_t a;
    asm("{ .reg .u64 t; cvta.to.shared.u64 t, %1; cvt.u32.u64 %0, t; }" : "=r"(a) : "l"(p));
    return a;
}
__device__ __forceinline__ float tf32r(float x) {
    uint32_t u;
    asm("cvt.rna.tf32.f32 %0, %1;" : "=r"(u) : "f"(x));
    return __uint_as_float(u);
}
__device__ __forceinline__ void mma_tf32(float c[4], const uint32_t a[4], const uint32_t b[2]) {
    asm volatile(
        "mma.sync.aligned.m16n8k8.row.col.f32.tf32.tf32.f32 "
        "{%0,%1,%2,%3}, {%4,%5,%6,%7}, {%8,%9}, {%0,%1,%2,%3};"
        : "+f"(c[0]), "+f"(c[1]), "+f"(c[2]), "+f"(c[3])
        : "r"(a[0]), "r"(a[1]), "r"(a[2]), "r"(a[3]), "r"(b[0]), "r"(b[1]));
}
__device__ __forceinline__ void ldsm4(uint32_t& r0, uint32_t& r1, uint32_t& r2, uint32_t& r3,
                                      uint32_t addr) {
    asm volatile("ldmatrix.sync.aligned.m8n8.x4.shared.b16 {%0,%1,%2,%3}, [%4];"
                 : "=r"(r0), "=r"(r1), "=r"(r2), "=r"(r3) : "r"(addr));
}

// ---------------- TF32 tensor-core GEMM (mma.sync + ldmatrix) ----------------
// C[z][m][n] = sum_k A[z][m][k] * B[z][n][k]    (both K-major)
// EPI: 0 plain, 1 scale+mask(-1e9), 2 +bias[n]
constexpr int BM = 128, BN = 128, BK = 32, BKP = 36;          // padded stride (floats)
constexpr int STG_FLT  = (BM + BN) * BKP;                     // floats per stage
constexpr int SMEM_DYN = 2 * STG_FLT * 4;                     // 73728 bytes

template <int EPI>
__global__ __launch_bounds__(256, 2)
void gemm_tf32(const float* __restrict__ Ag, const float* __restrict__ Bg,
               float* __restrict__ Cg,
               int N, int K, long long sA, long long sB, long long sC,
               const int* __restrict__ maskg, long long sMask,
               const float* __restrict__ bias, float scale)
{
    extern __shared__ float smem[];

    const int tid  = threadIdx.x;
    const int lane = tid & 31;
    const int warp = tid >> 5;
    const int wm = (warp & 1) * 64;       // 2 warps along M
    const int wn = (warp >> 1) * 32;      // 4 warps along N
    const int z  = blockIdx.z;
    const int m0 = blockIdx.y * BM;
    const int n0 = blockIdx.x * BN;

    const float* A = Ag + (size_t)z * sA;
    const float* B = Bg + (size_t)z * sB;

    const int lr = tid >> 3;              // 0..31
    const int lc = (tid & 7) * 4;         // 0,4,..,28

    // ldmatrix per-thread source rows / column-halves (byte offsets, stride 144B)
    const uint32_t sbase  = smem_u32(smem);
    const uint32_t aRowB  = (uint32_t)(wm + (lane & 15)) * (BKP * 4) + (uint32_t)(lane >> 4) * 16;
    const uint32_t bRowB  = (uint32_t)(wn + (lane & 7) + ((lane >> 4) << 3)) * (BKP * 4)
                          + (uint32_t)((lane >> 3) & 1) * 16;

    float acc[4][4][4];
#pragma unroll
    for (int i = 0; i < 4; i++)
#pragma unroll
        for (int j = 0; j < 4; j++)
#pragma unroll
            for (int r = 0; r < 4; r++) acc[i][j][r] = 0.0f;

    float4 ra[4], rb[4];
    const int KT = K / BK;

    // prologue: chunk 0 -> regs -> stage 0
#pragma unroll
    for (int i = 0; i < 4; i++) {
        ra[i] = *(const float4*)(A + (size_t)(m0 + lr + 32 * i) * K + lc);
        rb[i] = *(const float4*)(B + (size_t)(n0 + lr + 32 * i) * K + lc);
    }
#pragma unroll
    for (int i = 0; i < 4; i++) {
        float4 v = ra[i];
        v.x = tf32r(v.x); v.y = tf32r(v.y); v.z = tf32r(v.z); v.w = tf32r(v.w);
        *(float4*)&smem[(lr + 32 * i) * BKP + lc] = v;
        float4 w = rb[i];
        w.x = tf32r(w.x); w.y = tf32r(w.y); w.z = tf32r(w.z); w.w = tf32r(w.w);
        *(float4*)&smem[(BM + lr + 32 * i) * BKP + lc] = w;
    }
    __syncthreads();
    if (KT > 1) {
#pragma unroll
        for (int i = 0; i < 4; i++) {
            ra[i] = *(const float4*)(A + (size_t)(m0 + lr + 32 * i) * K + BK + lc);
            rb[i] = *(const float4*)(B + (size_t)(n0 + lr + 32 * i) * K + BK + lc);
        }
    }

    for (int kb = 0; kb < KT; ++kb) {
        const int cur = kb & 1;
        const uint32_t curBase = sbase + (uint32_t)cur * (STG_FLT * 4);
        const uint32_t aBase = curBase + aRowB;
        const uint32_t bBase = curBase + (uint32_t)(BM * BKP * 4) + bRowB;

        // stash chunk kb+1 (already in regs) into the other stage
        if (kb + 1 < KT) {
            float* dst = smem + (cur ^ 1) * STG_FLT;
#pragma unroll
            for (int i = 0; i < 4; i++) {
                float4 v = ra[i];
                v.x = tf32r(v.x); v.y = tf32r(v.y); v.z = tf32r(v.z); v.w = tf32r(v.w);
                *(float4*)&dst[(lr + 32 * i) * BKP + lc] = v;
                float4 w = rb[i];
                w.x = tf32r(w.x); w.y = tf32r(w.y); w.z = tf32r(w.z); w.w = tf32r(w.w);
                *(float4*)&dst[(BM + lr + 32 * i) * BKP + lc] = w;
            }
        }
        // issue LDGs for chunk kb+2
        if (kb + 2 < KT) {
            const int koff = (kb + 2) * BK + lc;
#pragma unroll
            for (int i = 0; i < 4; i++) {
                ra[i] = *(const float4*)(A + (size_t)(m0 + lr + 32 * i) * K + koff);
                rb[i] = *(const float4*)(B + (size_t)(n0 + lr + 32 * i) * K + koff);
            }
        }

        // compute on current stage: 4 k-steps of 8
#pragma unroll
        for (int ks = 0; ks < 4; ++ks) {
            const uint32_t kB = (uint32_t)ks * 32;   // ks*8 floats = 32 bytes
            uint32_t af[4][4], bf[4][2];
#pragma unroll
            for (int mi = 0; mi < 4; mi++)
                ldsm4(af[mi][0], af[mi][1], af[mi][2], af[mi][3],
                      aBase + (uint32_t)mi * (16 * BKP * 4) + kB);
#pragma unroll
            for (int pr = 0; pr < 2; pr++)
                ldsm4(bf[2 * pr][0], bf[2 * pr][1], bf[2 * pr + 1][0], bf[2 * pr + 1][1],
                      bBase + (uint32_t)pr * (16 * BKP * 4) + kB);
#pragma unroll
            for (int mi = 0; mi < 4; mi++)
#pragma unroll
                for (int ni = 0; ni < 4; ni++)
                    mma_tf32(acc[mi][ni], af[mi], bf[ni]);
        }
        __syncthreads();
    }

    // ---------------- epilogue ----------------
    float* C = Cg + (size_t)z * sC;
    const int* Mk = (EPI == 1) ? (maskg + (size_t)z * sMask) : (const int*)0;

#pragma unroll
    for (int mi = 0; mi < 4; mi++) {
#pragma unroll
        for (int ni = 0; ni < 4; ni++) {
            const int row0 = m0 + wm + mi * 16 + (lane >> 2);
            const int col  = n0 + wn + ni * 8 + (lane & 3) * 2;
#pragma unroll
            for (int h = 0; h < 2; ++h) {
                const int row = row0 + h * 8;
                float v0 = acc[mi][ni][2 * h];
                float v1 = acc[mi][ni][2 * h + 1];
                if (EPI == 1) {
                    v0 *= scale; v1 *= scale;
                    int2 mk = *(const int2*)(Mk + (size_t)row * N + col);
                    if (mk.x == 0) v0 = NEGF;
                    if (mk.y == 0) v1 = NEGF;
                } else if (EPI == 2) {
                    v0 += bias[col];
                    v1 += bias[col + 1];
                }
                float2 o; o.x = v0; o.y = v1;
                *(float2*)(C + (size_t)row * N + col) = o;
            }
        }
    }
}

// ---------------- row softmax over NK=2048 ----------------
__global__ __launch_bounds__(256)
void softmax_rows(float* __restrict__ S)
{
    float* row = S + (size_t)blockIdx.x * 2048;
    const int tid = threadIdx.x;

    float4 a = reinterpret_cast<float4*>(row)[tid];
    float4 b = reinterpret_cast<float4*>(row)[tid + 256];

    float m = fmaxf(fmaxf(fmaxf(a.x, a.y), fmaxf(a.z, a.w)),
                    fmaxf(fmaxf(b.x, b.y), fmaxf(b.z, b.w)));
#pragma unroll
    for (int o = 16; o; o >>= 1) m = fmaxf(m, __shfl_xor_sync(0xffffffffu, m, o));

    __shared__ float red[8];
    if ((tid & 31) == 0) red[tid >> 5] = m;
    __syncthreads();
    m = red[0];
#pragma unroll
    for (int i = 1; i < 8; i++) m = fmaxf(m, red[i]);

    a.x = __expf(a.x - m); a.y = __expf(a.y - m); a.z = __expf(a.z - m); a.w = __expf(a.w - m);
    b.x = __expf(b.x - m); b.y = __expf(b.y - m); b.z = __expf(b.z - m); b.w = __expf(b.w - m);

    float s = (a.x + a.y) + (a.z + a.w) + (b.x + b.y) + (b.z + b.w);
#pragma unroll
    for (int o = 16; o; o >>= 1) s += __shfl_xor_sync(0xffffffffu, s, o);

    __syncthreads();
    if ((tid & 31) == 0) red[tid >> 5] = s;
    __syncthreads();
    s = red[0];
#pragma unroll
    for (int i = 1; i < 8; i++) s += red[i];

    const float inv = 1.0f / s;
    a.x *= inv; a.y *= inv; a.z *= inv; a.w *= inv;
    b.x *= inv; b.y *= inv; b.z *= inv; b.w *= inv;

    reinterpret_cast<float4*>(row)[tid]       = a;
    reinterpret_cast<float4*>(row)[tid + 256] = b;
}

// ---------------- launch ----------------
extern "C" void kernel_launch(void* const* d_in, const int* in_sizes, int n_in,
                              void* d_out, int out_size)
{
    const float* keys    = (const float*)d_in[0];   // [16, 2048, 512]
    const float* queries = (const float*)d_in[1];   // [16, 1024, 512]
    const float* values  = (const float*)d_in[2];   // [16, 2048, 512]
    const int*   mask    = (const int*)  d_in[3];   // [16, 1024, 2048]
    const float* W       = (const float*)d_in[4];   // [256, 512]
    const float* bias    = (const float*)d_in[5];   // [256]
    float* out = (float*)d_out;                     // [16, 1024, 256]

    const int B = 16, NQ = 1024, NK = 2048, D = 512, V = 512, O = 256;
    const float scale = 1.0f / sqrtf(512.0f);       // KQ = 512

    float* S = nullptr;  float* Vt = nullptr;
    cudaGetSymbolAddress((void**)&S,  g_S);
    cudaGetSymbolAddress((void**)&Vt, g_Vt);

    cudaFuncSetAttribute(gemm_tf32<0>, cudaFuncAttributeMaxDynamicSharedMemorySize, SMEM_DYN);
    cudaFuncSetAttribute(gemm_tf32<1>, cudaFuncAttributeMaxDynamicSharedMemorySize, SMEM_DYN);
    cudaFuncSetAttribute(gemm_tf32<2>, cudaFuncAttributeMaxDynamicSharedMemorySize, SMEM_DYN);

    // K0: Vt[b][o][n] = sum_v W[o][v] * values[b][n][v]
    gemm_tf32<0><<<dim3(NK / BN, O / BM, B), 256, SMEM_DYN>>>(
        W, values, Vt, NK, V,
        0LL, (long long)NK * V, (long long)O * NK,
        nullptr, 0LL, nullptr, 0.0f);

    // K1: S[b][q][k] = scale * <Q,K>, mask==0 -> -1e9
    gemm_tf32<1><<<dim3(NK / BN, NQ / BM, B), 256, SMEM_DYN>>>(
        queries, keys, S, NK, D,
        (long long)NQ * D, (long long)NK * D, (long long)NQ * NK,
        mask, (long long)NQ * NK, nullptr, scale);

    // K2: softmax over last dim
    softmax_rows<<<B * NQ, 256>>>(S);

    // K3: out[b][q][o] = sum_k P[b][q][k] * Vt[b][o][k] + bias[o]
    gemm_tf32<2><<<dim3(O / BN, NQ / BM, B), 256, SMEM_DYN>>>(
        S, Vt, out, O, NK,
        (long long)NQ * NK, (long long)O * NK, (long long)NQ * O,
        nullptr, 0LL, bias, 1.0f);
}

// round 4
// speedup vs baseline: 1.0635x; 1.0129x over previous
#include <cuda_runtime.h>
#include <stdint.h>

#define NEGF (-1e9f)

// ---------------- scratch (alloc-free: __device__ globals) ----------------
__device__ float g_S [16u * 1024u * 2048u];   // logits / probs  [B,NQ,NK]
__device__ float g_Vt[16u * 256u  * 2048u];   // V'^T = W @ V^T  [B,O,NK]

// ---------------- helpers ----------------
__device__ __forceinline__ uint32_t smem_u32(const void* p) {
    uint32_t a;
    asm("{ .reg .u64 t; cvta.to.shared.u64 t, %1; cvt.u32.u64 %0, t; }" : "=r"(a) : "l"(p));
    return a;
}
__device__ __forceinline__ float tf32r(float x) {
    uint32_t u;
    asm("cvt.rna.tf32.f32 %0, %1;" : "=r"(u) : "f"(x));
    return __uint_as_float(u);
}
__device__ __forceinline__ void mma_tf32(float c[4], const uint32_t a[4], const uint32_t b[2]) {
    asm volatile(
        "mma.sync.aligned.m16n8k8.row.col.f32.tf32.tf32.f32 "
        "{%0,%1,%2,%3}, {%4,%5,%6,%7}, {%8,%9}, {%0,%1,%2,%3};"
        : "+f"(c[0]), "+f"(c[1]), "+f"(c[2]), "+f"(c[3])
        : "r"(a[0]), "r"(a[1]), "r"(a[2]), "r"(a[3]), "r"(b[0]), "r"(b[1]));
}
__device__ __forceinline__ void ldsm4(uint32_t& r0, uint32_t& r1, uint32_t& r2, uint32_t& r3,
                                      uint32_t addr) {
    asm volatile("ldmatrix.sync.aligned.m8n8.x4.shared.b16 {%0,%1,%2,%3}, [%4];"
                 : "=r"(r0), "=r"(r1), "=r"(r2), "=r"(r3) : "r"(addr));
}

// ---------------- TF32 tensor-core GEMM (mma.sync + ldmatrix) ----------------
// C[z][m][n] = sum_k A[z][m][k] * B[z][n][k]    (both K-major)
// EPI: 0 plain, 1 scale+mask(-1e9), 2 +bias[n]
// CTA tile 128x256x32, 8 warps as 2(M) x 4(N), warp tile 64x64.
constexpr int BM = 128, BN = 256, BK = 32, BKP = 36;          // padded stride (floats)
constexpr int STG_FLT  = (BM + BN) * BKP;                     // floats per stage
constexpr int SMEM_DYN = 2 * STG_FLT * 4;                     // 110592 bytes

template <int EPI>
__global__ __launch_bounds__(256)
void gemm_tf32(const float* __restrict__ Ag, const float* __restrict__ Bg,
               float* __restrict__ Cg,
               int N, int K, long long sA, long long sB, long long sC,
               const int* __restrict__ maskg, long long sMask,
               const float* __restrict__ bias, float scale)
{
    extern __shared__ float smem[];

    const int tid  = threadIdx.x;
    const int lane = tid & 31;
    const int warp = tid >> 5;
    const int wm = (warp & 1) * 64;       // 2 warps along M
    const int wn = (warp >> 1) * 64;      // 4 warps along N, 64 cols each
    const int z  = blockIdx.z;
    const int m0 = blockIdx.y * BM;
    const int n0 = blockIdx.x * BN;

    const float* A = Ag + (size_t)z * sA;
    const float* B = Bg + (size_t)z * sB;

    const int lr = tid >> 3;              // 0..31
    const int lc = (tid & 7) * 4;         // 0,4,..,28

    // ldmatrix per-thread byte offsets (smem row stride = BKP*4 = 144B)
    const uint32_t sbase  = smem_u32(smem);
    const uint32_t aRowB  = (uint32_t)(wm + (lane & 15)) * (BKP * 4) + (uint32_t)(lane >> 4) * 16;
    const uint32_t bRowB  = (uint32_t)(wn + (lane & 7) + ((lane >> 4) << 3)) * (BKP * 4)
                          + (uint32_t)((lane >> 3) & 1) * 16;

    float acc[4][8][4];
#pragma unroll
    for (int i = 0; i < 4; i++)
#pragma unroll
        for (int j = 0; j < 8; j++)
#pragma unroll
            for (int r = 0; r < 4; r++) acc[i][j][r] = 0.0f;

    float4 ra[4], rb[8];
    const int KT = K / BK;

    // prologue: chunk 0 -> regs -> stage 0
#pragma unroll
    for (int i = 0; i < 4; i++)
        ra[i] = *(const float4*)(A + (size_t)(m0 + lr + 32 * i) * K + lc);
#pragma unroll
    for (int i = 0; i < 8; i++) {
        int f = tid + 256 * i, r = f >> 3, qq = (f & 7) * 4;
        rb[i] = *(const float4*)(B + (size_t)(n0 + r) * K + qq);
    }
#pragma unroll
    for (int i = 0; i < 4; i++) {
        float4 v = ra[i];
        v.x = tf32r(v.x); v.y = tf32r(v.y); v.z = tf32r(v.z); v.w = tf32r(v.w);
        *(float4*)&smem[(lr + 32 * i) * BKP + lc] = v;
    }
#pragma unroll
    for (int i = 0; i < 8; i++) {
        int f = tid + 256 * i, r = f >> 3, qq = (f & 7) * 4;
        float4 w = rb[i];
        w.x = tf32r(w.x); w.y = tf32r(w.y); w.z = tf32r(w.z); w.w = tf32r(w.w);
        *(float4*)&smem[(BM + r) * BKP + qq] = w;
    }
    __syncthreads();
    if (KT > 1) {
#pragma unroll
        for (int i = 0; i < 4; i++)
            ra[i] = *(const float4*)(A + (size_t)(m0 + lr + 32 * i) * K + BK + lc);
#pragma unroll
        for (int i = 0; i < 8; i++) {
            int f = tid + 256 * i, r = f >> 3, qq = (f & 7) * 4;
            rb[i] = *(const float4*)(B + (size_t)(n0 + r) * K + BK + qq);
        }
    }

    for (int kb = 0; kb < KT; ++kb) {
        const int cur = kb & 1;
        const uint32_t curBase = sbase + (uint32_t)cur * (STG_FLT * 4);
        const uint32_t aBase = curBase + aRowB;
        const uint32_t bBase = curBase + (uint32_t)(BM * BKP * 4) + bRowB;

        // stash chunk kb+1 (already in regs) into the other stage
        if (kb + 1 < KT) {
            float* dst = smem + (cur ^ 1) * STG_FLT;
#pragma unroll
            for (int i = 0; i < 4; i++) {
                float4 v = ra[i];
                v.x = tf32r(v.x); v.y = tf32r(v.y); v.z = tf32r(v.z); v.w = tf32r(v.w);
                *(float4*)&dst[(lr + 32 * i) * BKP + lc] = v;
            }
#pragma unroll
            for (int i = 0; i < 8; i++) {
                int f = tid + 256 * i, r = f >> 3, qq = (f & 7) * 4;
                float4 w = rb[i];
                w.x = tf32r(w.x); w.y = tf32r(w.y); w.z = tf32r(w.z); w.w = tf32r(w.w);
                *(float4*)&dst[(BM + r) * BKP + qq] = w;
            }
        }
        // issue LDGs for chunk kb+2
        if (kb + 2 < KT) {
            const int koff = (kb + 2) * BK;
#pragma unroll
            for (int i = 0; i < 4; i++)
                ra[i] = *(const float4*)(A + (size_t)(m0 + lr + 32 * i) * K + koff + lc);
#pragma unroll
            for (int i = 0; i < 8; i++) {
                int f = tid + 256 * i, r = f >> 3, qq = (f & 7) * 4;
                rb[i] = *(const float4*)(B + (size_t)(n0 + r) * K + koff + qq);
            }
        }

        // compute on current stage: 4 k-steps of 8
#pragma unroll
        for (int ks = 0; ks < 4; ++ks) {
            const uint32_t kB = (uint32_t)ks * 32;   // ks*8 floats = 32 bytes
            uint32_t af[4][4], bf[8][2];
#pragma unroll
            for (int mi = 0; mi < 4; mi++)
                ldsm4(af[mi][0], af[mi][1], af[mi][2], af[mi][3],
                      aBase + (uint32_t)mi * (16 * BKP * 4) + kB);
#pragma unroll
            for (int pr = 0; pr < 4; pr++)
                ldsm4(bf[2 * pr][0], bf[2 * pr][1], bf[2 * pr + 1][0], bf[2 * pr + 1][1],
                      bBase + (uint32_t)pr * (16 * BKP * 4) + kB);
#pragma unroll
            for (int mi = 0; mi < 4; mi++)
#pragma unroll
                for (int ni = 0; ni < 8; ni++)
                    mma_tf32(acc[mi][ni], af[mi], bf[ni]);
        }
        __syncthreads();
    }

    // ---------------- epilogue ----------------
    float* C = Cg + (size_t)z * sC;
    const int* Mk = (EPI == 1) ? (maskg + (size_t)z * sMask) : (const int*)0;

#pragma unroll
    for (int mi = 0; mi < 4; mi++) {
#pragma unroll
        for (int ni = 0; ni < 8; ni++) {
            const int row0 = m0 + wm + mi * 16 + (lane >> 2);
            const int col  = n0 + wn + ni * 8 + (lane & 3) * 2;
#pragma unroll
            for (int h = 0; h < 2; ++h) {
                const int row = row0 + h * 8;
                float v0 = acc[mi][ni][2 * h];
                float v1 = acc[mi][ni][2 * h + 1];
                if (EPI == 1) {
                    v0 *= scale; v1 *= scale;
                    int2 mk = *(const int2*)(Mk + (size_t)row * N + col);
                    if (mk.x == 0) v0 = NEGF;
                    if (mk.y == 0) v1 = NEGF;
                } else if (EPI == 2) {
                    v0 += bias[col];
                    v1 += bias[col + 1];
                }
                float2 o; o.x = v0; o.y = v1;
                *(float2*)(C + (size_t)row * N + col) = o;
            }
        }
    }
}

// ---------------- row softmax over NK=2048 ----------------
__global__ __launch_bounds__(256)
void softmax_rows(float* __restrict__ S)
{
    float* row = S + (size_t)blockIdx.x * 2048;
    const int tid = threadIdx.x;

    float4 a = reinterpret_cast<float4*>(row)[tid];
    float4 b = reinterpret_cast<float4*>(row)[tid + 256];

    float m = fmaxf(fmaxf(fmaxf(a.x, a.y), fmaxf(a.z, a.w)),
                    fmaxf(fmaxf(b.x, b.y), fmaxf(b.z, b.w)));
#pragma unroll
    for (int o = 16; o; o >>= 1) m = fmaxf(m, __shfl_xor_sync(0xffffffffu, m, o));

    __shared__ float red[8];
    if ((tid & 31) == 0) red[tid >> 5] = m;
    __syncthreads();
    m = red[0];
#pragma unroll
    for (int i = 1; i < 8; i++) m = fmaxf(m, red[i]);

    a.x = __expf(a.x - m); a.y = __expf(a.y - m); a.z = __expf(a.z - m); a.w = __expf(a.w - m);
    b.x = __expf(b.x - m); b.y = __expf(b.y - m); b.z = __expf(b.z - m); b.w = __expf(b.w - m);

    float s = (a.x + a.y) + (a.z + a.w) + (b.x + b.y) + (b.z + b.w);
#pragma unroll
    for (int o = 16; o; o >>= 1) s += __shfl_xor_sync(0xffffffffu, s, o);

    __syncthreads();
    if ((tid & 31) == 0) red[tid >> 5] = s;
    __syncthreads();
    s = red[0];
#pragma unroll
    for (int i = 1; i < 8; i++) s += red[i];

    const float inv = 1.0f / s;
    a.x *= inv; a.y *= inv; a.z *= inv; a.w *= inv;
    b.x *= inv; b.y *= inv; b.z *= inv; b.w *= inv;

    reinterpret_cast<float4*>(row)[tid]       = a;
    reinterpret_cast<float4*>(row)[tid + 256] = b;
}

// ---------------- launch ----------------
extern "C" void kernel_launch(void* const* d_in, const int* in_sizes, int n_in,
                              void* d_out, int out_size)
{
    const float* keys    = (const float*)d_in[0];   // [16, 2048, 512]
    const float* queries = (const float*)d_in[1];   // [16, 1024, 512]
    const float* values  = (const float*)d_in[2];   // [16, 2048, 512]
    const int*   mask    = (const int*)  d_in[3];   // [16, 1024, 2048]
    const float* W       = (const float*)d_in[4];   // [256, 512]
    const float* bias    = (const float*)d_in[5];   // [256]
    float* out = (float*)d_out;                     // [16, 1024, 256]

    const int B = 16, NQ = 1024, NK = 2048, D = 512, V = 512, O = 256;
    const float scale = 1.0f / sqrtf(512.0f);       // KQ = 512

    float* S = nullptr;  float* Vt = nullptr;
    cudaGetSymbolAddress((void**)&S,  g_S);
    cudaGetSymbolAddress((void**)&Vt, g_Vt);

    cudaFuncSetAttribute(gemm_tf32<0>, cudaFuncAttributeMaxDynamicSharedMemorySize, SMEM_DYN);
    cudaFuncSetAttribute(gemm_tf32<1>, cudaFuncAttributeMaxDynamicSharedMemorySize, SMEM_DYN);
    cudaFuncSetAttribute(gemm_tf32<2>, cudaFuncAttributeMaxDynamicSharedMemorySize, SMEM_DYN);

    // K0: Vt[b][o][n] = sum_v W[o][v] * values[b][n][v]
    gemm_tf32<0><<<dim3(NK / BN, O / BM, B), 256, SMEM_DYN>>>(
        W, values, Vt, NK, V,
        0LL, (long long)NK * V, (long long)O * NK,
        nullptr, 0LL, nullptr, 0.0f);

    // K1: S[b][q][k] = scale * <Q,K>, mask==0 -> -1e9
    gemm_tf32<1><<<dim3(NK / BN, NQ / BM, B), 256, SMEM_DYN>>>(
        queries, keys, S, NK, D,
        (long long)NQ * D, (long long)NK * D, (long long)NQ * NK,
        mask, (long long)NQ * NK, nullptr, scale);

    // K2: softmax over last dim
    softmax_rows<<<B * NQ, 256>>>(S);

    // K3: out[b][q][o] = sum_k P[b][q][k] * Vt[b][o][k] + bias[o]
    gemm_tf32<2><<<dim3(O / BN, NQ / BM, B), 256, SMEM_DYN>>>(
        S, Vt, out, O, NK,
        (long long)NQ * NK, (long long)O * NK, (long long)NQ * O,
        nullptr, 0LL, bias, 1.0f);
}